// round 12
// baseline (speedup 1.0000x reference)
#include <cuda_runtime.h>
#include <cuda_fp16.h>
#include <cstdint>

#define B   128
#define T   256
#define DIN 512
#define H   1024
#define S   128
#define DH  1024

#define AZ_IMGS 18                       // images per step slot: 2 z + 16 h
#define AZ_SLOT (AZ_IMGS * 8192)         // halves per slot

// ---- scratch (fp16 image layout: tiles of 128 rows x 64 halves, XOR-swizzled) ----
__device__ __half  g_az[(size_t)(T + 1) * AZ_SLOT];  // activation slots: [z0 z1 h0..h15]
__device__ float   g_c[B * H];                       // cell, fp32 linear
__device__ __half  g_hid[(size_t)B * T * DH];        // [256 rt][16 c][128x64]
__device__ float   g_P[(size_t)B * T * 256];         // x-part of posterior, fp32 linear
__device__ __half  g_xri[(size_t)B * T * DIN];       // [256 rt][8 c][128x64]
__device__ __half  g_Wp[256 * 18 * 1024];            // lstm W [256 nt][18 c][16x64]
__device__ float   g_bp[4096];                       // bih+bhh gate-interleaved
__device__ __half  g_Wmvh[32 * 16 * 512];            // post W h-part [32 nt][16 c][8x64]
__device__ __half  g_Wmvx[4 * 8 * 4096];             // postx W [4 nt][8 c][64x64]
__device__ __half  g_Wd1i[16 * 2 * 4096];            // [16 nt][2 c][64x64]
__device__ __half  g_Wd2i[8 * 16 * 4096];            // [8 nt][16 c][64x64]
__device__ double  g_klpart[T * 32];

// ======================= helpers =======================
__device__ __forceinline__ uint32_t smem_u32(const void* p) {
    uint32_t a;
    asm("{ .reg .u64 t; cvta.to.shared.u64 t, %1; cvt.u32.u64 %0, t; }" : "=r"(a) : "l"(p));
    return a;
}
// swizzled offset (halves) of (row, k) inside a [rows x 64] fp16 tile image
__device__ __forceinline__ int imgoff16(int row, int k) {
    return row * 64 + ((((k >> 3) ^ row) & 7) << 3) + (k & 7);
}

#define MBAR_INIT(a, c) \
    asm volatile("mbarrier.init.shared.b64 [%0], %1;" :: "r"(a), "r"(c) : "memory")

#define MBAR_WAIT(a, ph) do {                                                   \
    uint32_t _m = (a), _p = (uint32_t)(ph), _d;                                 \
    asm volatile("{\n\t.reg .pred p;\n\t"                                       \
        "mbarrier.try_wait.parity.acquire.cta.shared::cta.b64 p, [%1], %2;\n\t" \
        "selp.b32 %0, 1, 0, p;\n\t}"                                            \
        : "=r"(_d) : "r"(_m), "r"(_p) : "memory");                              \
    if (!_d) {                                                                  \
        asm volatile("{\n\t.reg .pred P1;\n\t"                                  \
        "WL%=:\n\t"                                                             \
        "mbarrier.try_wait.parity.acquire.cta.shared::cta.b64 P1, [%0], %1, 0x989680;\n\t" \
        "@P1 bra.uni WD%=;\n\t"                                                 \
        "bra.uni WL%=;\n\t"                                                     \
        "WD%=:\n\t}"                                                            \
        :: "r"(_m), "r"(_p) : "memory");                                        \
    } } while (0)

#define EXPECT_TX(mb, n) \
    asm volatile("mbarrier.arrive.expect_tx.shared.b64 _, [%0], %1;" \
                 :: "r"(mb), "r"((uint32_t)(n)) : "memory")
#define BULK_G2S(dst, src, n, mb) \
    asm volatile("cp.async.bulk.shared::cluster.global.mbarrier::complete_tx::bytes " \
                 "[%0], [%1], %2, [%3];" \
                 :: "r"(dst), "l"(src), "r"((uint32_t)(n)), "r"(mb) : "memory")

__device__ __forceinline__ void ldsm4(uint32_t (&r)[4], uint32_t a) {
    asm volatile("ldmatrix.sync.aligned.m8n8.x4.shared.b16 {%0,%1,%2,%3}, [%4];"
                 : "=r"(r[0]), "=r"(r[1]), "=r"(r[2]), "=r"(r[3]) : "r"(a));
}
__device__ __forceinline__ void ldsm2(uint32_t (&r)[2], uint32_t a) {
    asm volatile("ldmatrix.sync.aligned.m8n8.x2.shared.b16 {%0,%1}, [%2];"
                 : "=r"(r[0]), "=r"(r[1]) : "r"(a));
}
__device__ __forceinline__ void mma16(float (&d)[4], const uint32_t (&a)[4], const uint32_t* b) {
    asm volatile("mma.sync.aligned.m16n8k16.row.col.f32.f16.f16.f32 "
        "{%0,%1,%2,%3}, {%4,%5,%6,%7}, {%8,%9}, {%0,%1,%2,%3};"
        : "+f"(d[0]), "+f"(d[1]), "+f"(d[2]), "+f"(d[3])
        : "r"(a[0]), "r"(a[1]), "r"(a[2]), "r"(a[3]), "r"(b[0]), "r"(b[1]));
}
__device__ __forceinline__ float fsig(float x) {
    float xc = fminf(fmaxf(x, -30.f), 30.f);
    return __fdividef(1.f, 1.f + __expf(-xc));
}
__device__ __forceinline__ float ftanh(float x) {
    float xc = fminf(fmaxf(x, -15.f), 15.f);
    float e = __expf(-2.f * xc);
    return __fdividef(1.f - e, 1.f + e);
}

// ======================= bulk-DMA fp16 GEMM mainloop (KI-grouped chunks) =======================
// C[128, NT] += A[128, 64*KI*nchunks] @ W[NT, 64*KI*nchunks]^T, fp16 in, fp32 acc.
// Chunk = KI contiguous A images (KI*16KB) + KI contiguous W images (KI*NT*128B),
// loaded with exactly 2 bulk copies by thread 0 into an NS-stage mbarrier ring.
template<int NT, int NWM, int NWN, int MT, int NTT, int KI, int NS>
__device__ __forceinline__ void gemm_h(
    float (&acc)[MT][NTT][4],
    const __half* asrc, const __half* wsrc, int nchunks)
{
    extern __shared__ char smem[];
    constexpr uint32_t AB  = (uint32_t)KI * 16384u;
    constexpr uint32_t WB  = (uint32_t)KI * NT * 128u;
    constexpr uint32_t STG = AB + WB;
    const int tid = threadIdx.x;
    const int t = tid & 31, w = tid >> 5;
    const int wm = w % NWM, wn = w / NWM;
    const int m0 = wm * (128 / NWM), n0 = wn * (NT / NWN);
    const uint32_t ctrl = smem_u32(smem);
    const uint32_t base = ctrl + 128;

    #pragma unroll
    for (int mt = 0; mt < MT; mt++)
        #pragma unroll
        for (int nt = 0; nt < NTT; nt++)
            #pragma unroll
            for (int q = 0; q < 4; q++) acc[mt][nt][q] = 0.f;

    int arowb[MT], arx[MT];
    #pragma unroll
    for (int mt = 0; mt < MT; mt++) {
        int r = m0 + mt * 16 + (t & 7) + ((t >> 3) & 1) * 8;
        arowb[mt] = r * 128; arx[mt] = r & 7;
    }
    const int au0 = (t >> 4) & 1;
    constexpr int NP = (NTT + 1) / 2;
    int wrowb[NP], wrx[NP], wu0;
    if constexpr (NTT == 1) {
        int r = n0 + (t & 7);
        wrowb[0] = r * 128; wrx[0] = r & 7; wu0 = (t >> 3) & 1;
    } else {
        #pragma unroll
        for (int p = 0; p < NP; p++) {
            int r = n0 + p * 16 + (t & 7) + ((t >> 4) & 1) * 8;
            wrowb[p] = r * 128; wrx[p] = r & 7;
        }
        wu0 = (t >> 3) & 1;
    }

    if (tid == 0) {
        #pragma unroll
        for (int s = 0; s < NS; s++) MBAR_INIT(ctrl + s * 8, 1);
    }
    __syncthreads();

    auto issue = [&](int c) {
        uint32_t mb = ctrl + (uint32_t)(c % NS) * 8;
        uint32_t ab = base + (uint32_t)(c % NS) * STG;
        EXPECT_TX(mb, AB + WB);
        BULK_G2S(ab, asrc + (size_t)c * (KI * 8192), AB, mb);
        BULK_G2S(ab + AB, wsrc + (size_t)c * (KI * NT * 64), WB, mb);
    };
    if (tid == 0)
        for (int i = 0; i < NS - 1 && i < nchunks; i++) issue(i);

    for (int c = 0; c < nchunks; c++) {
        __syncthreads();                       // all threads done with chunk c-1
        if (tid == 0 && c + NS - 1 < nchunks) issue(c + NS - 1);
        int st = c % NS, ph = (c / NS) & 1;
        MBAR_WAIT(ctrl + (uint32_t)st * 8, ph);
        uint32_t ab = base + (uint32_t)st * STG, wb = ab + AB;
        #pragma unroll
        for (int jj = 0; jj < 4 * KI; jj++) {
            const int img = jj >> 2, j = jj & 3;
            const uint32_t abj = ab + img * 16384;
            const uint32_t wbj = wb + img * (NT * 128);
            uint32_t afr[MT][4];
            #pragma unroll
            for (int mt = 0; mt < MT; mt++)
                ldsm4(afr[mt], abj + arowb[mt] + (((2 * j + au0) ^ arx[mt]) << 4));
            uint32_t bfr[NTT][2];
            if constexpr (NTT == 1) {
                uint32_t r2[2];
                ldsm2(r2, wbj + wrowb[0] + (((2 * j + wu0) ^ wrx[0]) << 4));
                bfr[0][0] = r2[0]; bfr[0][1] = r2[1];
            } else {
                #pragma unroll
                for (int p = 0; p < NP; p++) {
                    uint32_t r4[4];
                    ldsm4(r4, wbj + wrowb[p] + (((2 * j + wu0) ^ wrx[p]) << 4));
                    bfr[2 * p][0] = r4[0]; bfr[2 * p][1] = r4[1];
                    bfr[2 * p + 1][0] = r4[2]; bfr[2 * p + 1][1] = r4[3];
                }
            }
            #pragma unroll
            for (int mt = 0; mt < MT; mt++)
                #pragma unroll
                for (int nt = 0; nt < NTT; nt++)
                    mma16(acc[mt][nt], afr[mt], bfr[nt]);
        }
    }
}

// ======================= init / prepack =======================
__global__ void init_kernel() {
    int stride = gridDim.x * blockDim.x;
    int t0 = blockIdx.x * blockDim.x + threadIdx.x;
    uint32_t* a0 = (uint32_t*)&g_az[0];
    for (int i = t0; i < AZ_SLOT / 2; i += stride) a0[i] = 0u;   // slot 0: z=0, h=0
    for (int i = t0; i < B * H; i += stride) g_c[i] = 0.f;
}

__global__ void prepack_kernel(
    const float* __restrict__ x,
    const float* __restrict__ Wih, const float* __restrict__ Whh,
    const float* __restrict__ bih, const float* __restrict__ bhh,
    const float* __restrict__ Wm, const float* __restrict__ Wv,
    const float* __restrict__ Wd1, const float* __restrict__ Wd2)
{
    size_t stride = (size_t)gridDim.x * blockDim.x;
    size_t t0 = (size_t)blockIdx.x * blockDim.x + threadIdx.x;
    // lstm W: [256 nt][18 c][16x64]
    for (size_t i = t0; i < (size_t)256 * 18 * 1024; i += stride) {
        int k = (int)(i & 63), r = (int)((i >> 6) & 15);
        size_t tc = i >> 10;
        int c = (int)(tc % 18), nt = (int)(tc / 18);
        int gc = nt * 16 + r, j = gc >> 2, g = gc & 3, kc = c * 64 + k;
        float v = (kc < S) ? Wih[(size_t)(g * H + j) * S + kc]
                           : Whh[(size_t)(g * H + j) * H + (kc - S)];
        g_Wp[(tc << 10) + imgoff16(r, k)] = __float2half(v);
    }
    // post W h-part: [32 nt][16 c][8x64]
    for (size_t i = t0; i < (size_t)32 * 16 * 512; i += stride) {
        int k = (int)(i & 63), r = (int)((i >> 6) & 7);
        size_t tc = i >> 9;
        int c = (int)(tc & 15), nt = (int)(tc >> 4);
        int n = nt * 8 + r, col = 512 + c * 64 + k;
        const float* src = (n & 1) ? Wv : Wm;
        g_Wmvh[(tc << 9) + imgoff16(r, k)] = __float2half(src[(size_t)(n >> 1) * 1536 + col]);
    }
    // postx W x-part: [4 nt][8 c][64x64]
    for (size_t i = t0; i < (size_t)4 * 8 * 4096; i += stride) {
        int k = (int)(i & 63), r = (int)((i >> 6) & 63);
        size_t tc = i >> 12;
        int c = (int)(tc & 7), nt = (int)(tc >> 3);
        int n = nt * 64 + r, col = c * 64 + k;
        const float* src = (n & 1) ? Wv : Wm;
        g_Wmvx[(tc << 12) + imgoff16(r, k)] = __float2half(src[(size_t)(n >> 1) * 1536 + col]);
    }
    // Wd1: [16 nt][2 c][64x64]
    for (size_t i = t0; i < (size_t)16 * 2 * 4096; i += stride) {
        int k = (int)(i & 63), r = (int)((i >> 6) & 63);
        size_t tc = i >> 12;
        int c = (int)(tc & 1), nt = (int)(tc >> 1);
        g_Wd1i[(tc << 12) + imgoff16(r, k)] =
            __float2half(Wd1[(size_t)(nt * 64 + r) * S + c * 64 + k]);
    }
    // Wd2: [8 nt][16 c][64x64]
    for (size_t i = t0; i < (size_t)8 * 16 * 4096; i += stride) {
        int k = (int)(i & 63), r = (int)((i >> 6) & 63);
        size_t tc = i >> 12;
        int c = (int)(tc & 15), nt = (int)(tc >> 4);
        g_Wd2i[(tc << 12) + imgoff16(r, k)] =
            __float2half(Wd2[(size_t)(nt * 64 + r) * DH + c * 64 + k]);
    }
    // x images: [256 rt][8 c][128x64], row = b*T + t
    for (size_t i = t0; i < (size_t)256 * 8 * 8192; i += stride) {
        int k = (int)(i & 63), r = (int)((i >> 6) & 127);
        size_t tc = i >> 13;
        int c = (int)(tc & 7), rt = (int)(tc >> 3);
        size_t row = (size_t)rt * 128 + r;
        g_xri[(tc << 13) + imgoff16(r, k)] = __float2half(x[row * DIN + c * 64 + k]);
    }
    for (size_t i = t0; i < 4096; i += stride) {
        int j = (int)(i >> 2), g = (int)(i & 3);
        g_bp[i] = bih[g * H + j] + bhh[g * H + j];
    }
}

// ======================= LSTM step: 256 CTAs x N16 (2 CTAs/SM), fused pointwise =======================
__global__ __launch_bounds__(256) void lstm_k(
    const __half* __restrict__ azin, __half* __restrict__ hout)
{
    float acc[2][1][4];
    gemm_h<16, 4, 2, 2, 1, 2, 3>(acc, azin,
                                 g_Wp + (size_t)blockIdx.x * 18 * 1024, 9);

    const int tid = threadIdx.x, t = tid & 31, w = tid >> 5;
    const int wm = w & 3, wn = w >> 2;
    const int m0 = wm * 32, n0 = wn * 8;
    const bool even = (t & 1) == 0;

    #pragma unroll
    for (int mt = 0; mt < 2; mt++)
        #pragma unroll
        for (int rh = 0; rh < 2; rh++) {
            float v0 = acc[mt][0][rh * 2], v1 = acc[mt][0][rh * 2 + 1];
            float p0 = __shfl_xor_sync(0xffffffffu, v0, 1);
            float p1 = __shfl_xor_sync(0xffffffffu, v1, 1);
            if (even) {
                int lc = n0 + 2 * (t & 3);
                int pcb = blockIdx.x * 16 + lc;        // gate-interleaved col
                int j = pcb >> 2;
                float4 bb = *(const float4*)&g_bp[pcb];
                int b = m0 + mt * 16 + (t >> 2) + rh * 8;
                float cold = g_c[b * H + j];
                float i_ = fsig(v0 + bb.x);
                float f_ = fsig(v1 + bb.y);
                float gg = ftanh(p0 + bb.z);
                float o_ = fsig(p1 + bb.w);
                float cn = f_ * cold + i_ * gg;
                g_c[b * H + j] = cn;
                hout[(j >> 6) * 8192 + imgoff16(b, j & 63)] = __float2half(o_ * ftanh(cn));
            }
        }
}

// ======================= posterior step: 32 CTAs x N8 (h-part) =======================
__global__ __launch_bounds__(256) void post_k(
    const float* __restrict__ noise,
    const float* __restrict__ bm, const float* __restrict__ bv,
    const __half* __restrict__ hin, __half* __restrict__ zout, int ts)
{
    float acc[1][1][4];
    gemm_h<8, 8, 1, 1, 1, 4, 3>(acc, hin,
                                g_Wmvh + (size_t)blockIdx.x * 16 * 512, 4);

    __shared__ double klw[8];
    const int tid = threadIdx.x, t = tid & 31, w = tid >> 5;
    const int m0 = w * 16, tig = t & 3;
    const int s = blockIdx.x * 4 + tig;
    const float bms = bm[s], bvs = bv[s];
    float kl = 0.f;
    #pragma unroll
    for (int rh = 0; rh < 2; rh++) {
        int b = m0 + (t >> 2) + rh * 8;
        const float* pp = g_P + ((size_t)b * T + ts) * 256 + blockIdx.x * 8 + 2 * tig;
        float mean = acc[0][0][rh * 2]     + pp[0] + bms;
        float lv   = acc[0][0][rh * 2 + 1] + pp[1] + bvs;
        float sd = __expf(0.5f * fminf(fmaxf(lv, -80.f), 80.f));
        float nz = noise[((size_t)b * T + ts) * S + s];
        zout[(s >> 6) * 8192 + imgoff16(b, s & 63)] = __float2half(nz * sd + mean);
        kl += sd * sd + mean * mean - 0.5f * lv - 0.5f;
    }
    #pragma unroll
    for (int o = 16; o; o >>= 1) kl += __shfl_down_sync(0xffffffffu, kl, o);
    if (t == 0) klw[w] = (double)kl;
    __syncthreads();
    if (tid == 0) {
        double ssum = 0.0;
        #pragma unroll
        for (int i = 0; i < 8; i++) ssum += klw[i];
        g_klpart[(size_t)ts * 32 + blockIdx.x] = ssum;
    }
}

// ======================= postx: P = X @ Wmv[:, :512]^T (all t) =======================
__global__ __launch_bounds__(256) void postx_k() {
    float acc[2][4][4];
    gemm_h<64, 4, 2, 2, 4, 2, 3>(acc, g_xri + (size_t)blockIdx.y * 8 * 8192,
                                 g_Wmvx + (size_t)blockIdx.x * 8 * 4096, 4);
    const int tid = threadIdx.x, t = tid & 31, w = tid >> 5;
    const int wm = w & 3, wn = w >> 2;
    const int nb = blockIdx.x * 64, rb = blockIdx.y * 128;
    #pragma unroll
    for (int mt = 0; mt < 2; mt++)
        #pragma unroll
        for (int nt = 0; nt < 4; nt++)
            #pragma unroll
            for (int rh = 0; rh < 2; rh++) {
                int row = rb + wm * 32 + mt * 16 + (t >> 2) + rh * 8;
                int col = nb + wn * 32 + nt * 8 + 2 * (t & 3);
                *(float2*)&g_P[(size_t)row * 256 + col] =
                    make_float2(acc[mt][nt][rh * 2], acc[mt][nt][rh * 2 + 1]);
            }
}

// ======================= decoder =======================
__global__ __launch_bounds__(256) void dec1_k(const float* __restrict__ bd1) {
    float acc[2][4][4];
    // A = z images of step blockIdx.y: g_az slot (y+1), images 0..1 (32KB, one chunk)
    gemm_h<64, 4, 2, 2, 4, 2, 2>(acc, g_az + (size_t)(blockIdx.y + 1) * AZ_SLOT,
                                 g_Wd1i + (size_t)blockIdx.x * 2 * 4096, 1);
    const int tid = threadIdx.x, t = tid & 31, w = tid >> 5;
    const int wm = w & 3, wn = w >> 2;
    const int nb = blockIdx.x * 64, rb = blockIdx.y * 128;
    #pragma unroll
    for (int mt = 0; mt < 2; mt++)
        #pragma unroll
        for (int nt = 0; nt < 4; nt++)
            #pragma unroll
            for (int rh = 0; rh < 2; rh++) {
                int row = rb + wm * 32 + mt * 16 + (t >> 2) + rh * 8;   // t*128+b
                int col = nb + wn * 32 + nt * 8 + 2 * (t & 3);
                float v0 = fmaxf(acc[mt][nt][rh * 2]     + bd1[col],     0.f);
                float v1 = fmaxf(acc[mt][nt][rh * 2 + 1] + bd1[col + 1], 0.f);
                int rt = row >> 7, rr = row & 127;
                size_t off = ((size_t)(rt * 16 + (col >> 6)) << 13) + imgoff16(rr, col & 63);
                *(__half2*)&g_hid[off] = __floats2half2_rn(v0, v1);
            }
}

__global__ __launch_bounds__(256) void dec2_k(const float* __restrict__ bd2,
                                              float* __restrict__ out) {
    float acc[2][4][4];
    gemm_h<64, 4, 2, 2, 4, 2, 3>(acc, g_hid + (size_t)blockIdx.y * 16 * 8192,
                                 g_Wd2i + (size_t)blockIdx.x * 16 * 4096, 8);
    const int tid = threadIdx.x, t = tid & 31, w = tid >> 5;
    const int wm = w & 3, wn = w >> 2;
    const int nb = blockIdx.x * 64, rb = blockIdx.y * 128;
    #pragma unroll
    for (int mt = 0; mt < 2; mt++)
        #pragma unroll
        for (int nt = 0; nt < 4; nt++)
            #pragma unroll
            for (int rh = 0; rh < 2; rh++) {
                int row = rb + wm * 32 + mt * 16 + (t >> 2) + rh * 8;   // t*128+b
                int col = nb + wn * 32 + nt * 8 + 2 * (t & 3);
                int tt = row >> 7, bb = row & 127;
                float v0 = acc[mt][nt][rh * 2]     + bd2[col];
                float v1 = acc[mt][nt][rh * 2 + 1] + bd2[col + 1];
                *(float2*)&out[((size_t)bb * T + tt) * DIN + col] = make_float2(v0, v1);
            }
}

// ======================= final KL reduce =======================
__global__ void kl_kernel(float* __restrict__ out) {
    __shared__ double red[256];
    int tid = threadIdx.x;
    double ssum = 0.0;
    for (int i = tid; i < T * 32; i += 256) ssum += g_klpart[i];
    red[tid] = ssum;
    __syncthreads();
    for (int off = 128; off; off >>= 1) {
        if (tid < off) red[tid] += red[tid + off];
        __syncthreads();
    }
    if (tid == 0) out[(size_t)B * T * DIN] = (float)red[0];
}

// ======================= host =======================
extern "C" void kernel_launch(void* const* d_in, const int* in_sizes, int n_in,
                              void* d_out, int out_size)
{
    const float* x     = (const float*)d_in[0];
    const float* noise = (const float*)d_in[1];
    const float* Wih   = (const float*)d_in[2];
    const float* Whh   = (const float*)d_in[3];
    const float* bih   = (const float*)d_in[4];
    const float* bhh   = (const float*)d_in[5];
    const float* Wm    = (const float*)d_in[6];
    const float* bm    = (const float*)d_in[7];
    const float* Wv    = (const float*)d_in[8];
    const float* bv    = (const float*)d_in[9];
    const float* Wd1   = (const float*)d_in[10];
    const float* bd1   = (const float*)d_in[11];
    const float* Wd2   = (const float*)d_in[12];
    const float* bd2   = (const float*)d_in[13];
    float* out = (float*)d_out;

    const int SM_LSTM = 128 + 3 * (2 * 16384 + 2 * 2048);   // 110720 (-> 2 CTAs/SM)
    const int SM_POST = 128 + 3 * (4 * 16384 + 4 * 1024);   // 209024
    const int SM_BIG  = 128 + 3 * (2 * 16384 + 2 * 8192);   // 147584
    const int SM_DEC1 = 128 + 2 * (2 * 16384 + 2 * 8192);   //  98432
    cudaFuncSetAttribute(lstm_k,  cudaFuncAttributeMaxDynamicSharedMemorySize, SM_LSTM);
    cudaFuncSetAttribute(post_k,  cudaFuncAttributeMaxDynamicSharedMemorySize, SM_POST);
    cudaFuncSetAttribute(postx_k, cudaFuncAttributeMaxDynamicSharedMemorySize, SM_BIG);
    cudaFuncSetAttribute(dec1_k,  cudaFuncAttributeMaxDynamicSharedMemorySize, SM_DEC1);
    cudaFuncSetAttribute(dec2_k,  cudaFuncAttributeMaxDynamicSharedMemorySize, SM_BIG);

    __half* p_az;
    cudaGetSymbolAddress((void**)&p_az, g_az);

    init_kernel<<<256, 256>>>();
    prepack_kernel<<<1024, 256>>>(x, Wih, Whh, bih, bhh, Wm, Wv, Wd1, Wd2);
    postx_k<<<dim3(4, 256), 256, SM_BIG>>>();

    for (int t = 0; t < T; t++) {
        __half* slot_in  = p_az + (size_t)t * AZ_SLOT;
        __half* slot_out = p_az + (size_t)(t + 1) * AZ_SLOT;
        // lstm reads full slot t (z+h images), writes h images (2..17) of slot t+1
        lstm_k<<<256, 256, SM_LSTM>>>(slot_in, slot_out + 2 * 8192);
        // post reads h images of slot t+1, writes z images (0..1) of slot t+1
        post_k<<<32, 256, SM_POST>>>(noise, bm, bv, slot_out + 2 * 8192, slot_out, t);
    }
    dec1_k<<<dim3(16, 256), 256, SM_DEC1>>>(bd1);
    dec2_k<<<dim3(8, 256), 256, SM_BIG>>>(bd2, out);
    kl_kernel<<<1, 256>>>(out);
}

// round 13
// speedup vs baseline: 1.1144x; 1.1144x over previous
#include <cuda_runtime.h>
#include <cuda_fp16.h>
#include <cstdint>

#define B   128
#define T   256
#define DIN 512
#define H   1024
#define S   128
#define DH  1024

#define AZ_IMGS 18                       // images per step slot: 2 z + 16 h
#define AZ_SLOT (AZ_IMGS * 8192)         // halves per slot

// ---- scratch (fp16 image layout: tiles of 128 rows x 64 halves, XOR-swizzled) ----
__device__ __half  g_az[(size_t)(T + 1) * AZ_SLOT];  // activation slots: [z0 z1 h0..h15]
__device__ float   g_c[B * H];                       // cell, fp32 linear
__device__ __half  g_hid[(size_t)B * T * DH];        // [256 rt][16 c][128x64]
__device__ float   g_P[(size_t)B * T * 256];         // x-part of posterior, fp32 linear
__device__ __half  g_xri[(size_t)B * T * DIN];       // [256 rt][8 c][128x64]
__device__ __half  g_Wp[(size_t)64 * 18 * 4096];     // lstm W [64 nt][18 c][64x64]
__device__ float   g_bp[4096];                       // bih+bhh gate-interleaved
__device__ __half  g_Wmvh[16 * 16 * 1024];           // post W h-part [16 nt][16 c][16x64]
__device__ __half  g_Wmvx[4 * 8 * 4096];             // postx W [4 nt][8 c][64x64]
__device__ __half  g_Wd1i[16 * 2 * 4096];            // [16 nt][2 c][64x64]
__device__ __half  g_Wd2i[8 * 16 * 4096];            // [8 nt][16 c][64x64]
__device__ double  g_klpart[T * 32];

// ======================= helpers =======================
__device__ __forceinline__ uint32_t smem_u32(const void* p) {
    uint32_t a;
    asm("{ .reg .u64 t; cvta.to.shared.u64 t, %1; cvt.u32.u64 %0, t; }" : "=r"(a) : "l"(p));
    return a;
}
// swizzled offset (halves) of (row, k) inside a [rows x 64] fp16 tile image
__device__ __forceinline__ int imgoff16(int row, int k) {
    return row * 64 + ((((k >> 3) ^ row) & 7) << 3) + (k & 7);
}

#define MBAR_INIT(a, c) \
    asm volatile("mbarrier.init.shared.b64 [%0], %1;" :: "r"(a), "r"(c) : "memory")

#define MBAR_WAIT(a, ph) do {                                                   \
    uint32_t _m = (a), _p = (uint32_t)(ph), _d;                                 \
    asm volatile("{\n\t.reg .pred p;\n\t"                                       \
        "mbarrier.try_wait.parity.acquire.cta.shared::cta.b64 p, [%1], %2;\n\t" \
        "selp.b32 %0, 1, 0, p;\n\t}"                                            \
        : "=r"(_d) : "r"(_m), "r"(_p) : "memory");                              \
    if (!_d) {                                                                  \
        asm volatile("{\n\t.reg .pred P1;\n\t"                                  \
        "WL%=:\n\t"                                                             \
        "mbarrier.try_wait.parity.acquire.cta.shared::cta.b64 P1, [%0], %1, 0x989680;\n\t" \
        "@P1 bra.uni WD%=;\n\t"                                                 \
        "bra.uni WL%=;\n\t"                                                     \
        "WD%=:\n\t}"                                                            \
        :: "r"(_m), "r"(_p) : "memory");                                        \
    } } while (0)

#define EXPECT_TX(mb, n) \
    asm volatile("mbarrier.arrive.expect_tx.shared.b64 _, [%0], %1;" \
                 :: "r"(mb), "r"((uint32_t)(n)) : "memory")
#define BULK_G2S(dst, src, n, mb) \
    asm volatile("cp.async.bulk.shared::cluster.global.mbarrier::complete_tx::bytes " \
                 "[%0], [%1], %2, [%3];" \
                 :: "r"(dst), "l"(src), "r"((uint32_t)(n)), "r"(mb) : "memory")

__device__ __forceinline__ void ldsm4(uint32_t (&r)[4], uint32_t a) {
    asm volatile("ldmatrix.sync.aligned.m8n8.x4.shared.b16 {%0,%1,%2,%3}, [%4];"
                 : "=r"(r[0]), "=r"(r[1]), "=r"(r[2]), "=r"(r[3]) : "r"(a));
}
__device__ __forceinline__ void ldsm2(uint32_t (&r)[2], uint32_t a) {
    asm volatile("ldmatrix.sync.aligned.m8n8.x2.shared.b16 {%0,%1}, [%2];"
                 : "=r"(r[0]), "=r"(r[1]) : "r"(a));
}
__device__ __forceinline__ void mma16(float (&d)[4], const uint32_t (&a)[4], const uint32_t* b) {
    asm volatile("mma.sync.aligned.m16n8k16.row.col.f32.f16.f16.f32 "
        "{%0,%1,%2,%3}, {%4,%5,%6,%7}, {%8,%9}, {%0,%1,%2,%3};"
        : "+f"(d[0]), "+f"(d[1]), "+f"(d[2]), "+f"(d[3])
        : "r"(a[0]), "r"(a[1]), "r"(a[2]), "r"(a[3]), "r"(b[0]), "r"(b[1]));
}
__device__ __forceinline__ float fsig(float x) {
    float xc = fminf(fmaxf(x, -30.f), 30.f);
    return __fdividef(1.f, 1.f + __expf(-xc));
}
__device__ __forceinline__ float ftanh(float x) {
    float xc = fminf(fmaxf(x, -15.f), 15.f);
    float e = __expf(-2.f * xc);
    return __fdividef(1.f - e, 1.f + e);
}

// ======================= bulk-DMA fp16 GEMM mainloop =======================
// C[AROWS, NT] += A[AROWS, 64*KI*nchunks] @ W[NT, 64*KI*nchunks]^T, fp16 in, fp32 acc.
// A images are AROWS-row slices taken from gmem images spaced a_stride halves apart
// (KI per-image bulk copies). W is a contiguous prepack (one bulk copy per chunk).
// NS-stage mbarrier ring, issued by thread 0.
template<int NT, int NWM, int NWN, int MT, int NTT, int KI, int NS, int AROWS>
__device__ __forceinline__ void gemm_h(
    float (&acc)[MT][NTT][4],
    const __half* asrc, size_t a_stride,
    const __half* wsrc, int nchunks)
{
    extern __shared__ char smem[];
    constexpr uint32_t AIMG = (uint32_t)AROWS * 128u;       // bytes per A slice
    constexpr uint32_t AB  = (uint32_t)KI * AIMG;
    constexpr uint32_t WB  = (uint32_t)KI * NT * 128u;
    constexpr uint32_t STG = AB + WB;
    const int tid = threadIdx.x;
    const int t = tid & 31, w = tid >> 5;
    const int wm = w % NWM, wn = w / NWM;
    const int m0 = wm * (AROWS / NWM), n0 = wn * (NT / NWN);
    const uint32_t ctrl = smem_u32(smem);
    const uint32_t base = ctrl + 128;

    #pragma unroll
    for (int mt = 0; mt < MT; mt++)
        #pragma unroll
        for (int nt = 0; nt < NTT; nt++)
            #pragma unroll
            for (int q = 0; q < 4; q++) acc[mt][nt][q] = 0.f;

    int arowb[MT], arx[MT];
    #pragma unroll
    for (int mt = 0; mt < MT; mt++) {
        int r = m0 + mt * 16 + (t & 7) + ((t >> 3) & 1) * 8;
        arowb[mt] = r * 128; arx[mt] = r & 7;
    }
    const int au0 = (t >> 4) & 1;
    constexpr int NP = (NTT + 1) / 2;
    int wrowb[NP], wrx[NP], wu0;
    if constexpr (NTT == 1) {
        int r = n0 + (t & 7);
        wrowb[0] = r * 128; wrx[0] = r & 7; wu0 = (t >> 3) & 1;
    } else {
        #pragma unroll
        for (int p = 0; p < NP; p++) {
            int r = n0 + p * 16 + (t & 7) + ((t >> 4) & 1) * 8;
            wrowb[p] = r * 128; wrx[p] = r & 7;
        }
        wu0 = (t >> 3) & 1;
    }

    if (tid == 0) {
        #pragma unroll
        for (int s = 0; s < NS; s++) MBAR_INIT(ctrl + s * 8, 1);
    }
    __syncthreads();

    auto issue = [&](int c) {
        uint32_t mb = ctrl + (uint32_t)(c % NS) * 8;
        uint32_t ab = base + (uint32_t)(c % NS) * STG;
        EXPECT_TX(mb, AB + WB);
        #pragma unroll
        for (int i = 0; i < KI; i++)
            BULK_G2S(ab + (uint32_t)i * AIMG,
                     asrc + (size_t)(c * KI + i) * a_stride, AIMG, mb);
        BULK_G2S(ab + AB, wsrc + (size_t)c * (KI * NT * 64), WB, mb);
    };
    if (tid == 0)
        for (int i = 0; i < NS - 1 && i < nchunks; i++) issue(i);

    for (int c = 0; c < nchunks; c++) {
        __syncthreads();                       // all threads done with chunk c-1
        if (tid == 0 && c + NS - 1 < nchunks) issue(c + NS - 1);
        int st = c % NS, ph = (c / NS) & 1;
        MBAR_WAIT(ctrl + (uint32_t)st * 8, ph);
        uint32_t ab = base + (uint32_t)st * STG, wb = ab + AB;
        #pragma unroll
        for (int jj = 0; jj < 4 * KI; jj++) {
            const int img = jj >> 2, j = jj & 3;
            const uint32_t abj = ab + img * AIMG;
            const uint32_t wbj = wb + img * (NT * 128);
            uint32_t afr[MT][4];
            #pragma unroll
            for (int mt = 0; mt < MT; mt++)
                ldsm4(afr[mt], abj + arowb[mt] + (((2 * j + au0) ^ arx[mt]) << 4));
            uint32_t bfr[NTT][2];
            if constexpr (NTT == 1) {
                uint32_t r2[2];
                ldsm2(r2, wbj + wrowb[0] + (((2 * j + wu0) ^ wrx[0]) << 4));
                bfr[0][0] = r2[0]; bfr[0][1] = r2[1];
            } else {
                #pragma unroll
                for (int p = 0; p < NP; p++) {
                    uint32_t r4[4];
                    ldsm4(r4, wbj + wrowb[p] + (((2 * j + wu0) ^ wrx[p]) << 4));
                    bfr[2 * p][0] = r4[0]; bfr[2 * p][1] = r4[1];
                    bfr[2 * p + 1][0] = r4[2]; bfr[2 * p + 1][1] = r4[3];
                }
            }
            #pragma unroll
            for (int mt = 0; mt < MT; mt++)
                #pragma unroll
                for (int nt = 0; nt < NTT; nt++)
                    mma16(acc[mt][nt], afr[mt], bfr[nt]);
        }
    }
}

// ======================= init / prepack =======================
__global__ void init_kernel() {
    int stride = gridDim.x * blockDim.x;
    int t0 = blockIdx.x * blockDim.x + threadIdx.x;
    uint32_t* a0 = (uint32_t*)&g_az[0];
    for (int i = t0; i < AZ_SLOT / 2; i += stride) a0[i] = 0u;   // slot 0: z=0, h=0
    for (int i = t0; i < B * H; i += stride) g_c[i] = 0.f;
}

__global__ void prepack_kernel(
    const float* __restrict__ x,
    const float* __restrict__ Wih, const float* __restrict__ Whh,
    const float* __restrict__ bih, const float* __restrict__ bhh,
    const float* __restrict__ Wm, const float* __restrict__ Wv,
    const float* __restrict__ Wd1, const float* __restrict__ Wd2)
{
    size_t stride = (size_t)gridDim.x * blockDim.x;
    size_t t0 = (size_t)blockIdx.x * blockDim.x + threadIdx.x;
    // lstm W: [64 nt][18 c][64x64]
    for (size_t i = t0; i < (size_t)64 * 18 * 4096; i += stride) {
        int k = (int)(i & 63), r = (int)((i >> 6) & 63);
        size_t tc = i >> 12;
        int c = (int)(tc % 18), nt = (int)(tc / 18);
        int gc = nt * 64 + r, j = gc >> 2, g = gc & 3, kc = c * 64 + k;
        float v = (kc < S) ? Wih[(size_t)(g * H + j) * S + kc]
                           : Whh[(size_t)(g * H + j) * H + (kc - S)];
        g_Wp[(tc << 12) + imgoff16(r, k)] = __float2half(v);
    }
    // post W h-part: [16 nt][16 c][16x64]
    for (size_t i = t0; i < (size_t)16 * 16 * 1024; i += stride) {
        int k = (int)(i & 63), r = (int)((i >> 6) & 15);
        size_t tc = i >> 10;
        int c = (int)(tc & 15), nt = (int)(tc >> 4);
        int n = nt * 16 + r, col = 512 + c * 64 + k;
        const float* src = (n & 1) ? Wv : Wm;
        g_Wmvh[(tc << 10) + imgoff16(r, k)] = __float2half(src[(size_t)(n >> 1) * 1536 + col]);
    }
    // postx W x-part: [4 nt][8 c][64x64]
    for (size_t i = t0; i < (size_t)4 * 8 * 4096; i += stride) {
        int k = (int)(i & 63), r = (int)((i >> 6) & 63);
        size_t tc = i >> 12;
        int c = (int)(tc & 7), nt = (int)(tc >> 3);
        int n = nt * 64 + r, col = c * 64 + k;
        const float* src = (n & 1) ? Wv : Wm;
        g_Wmvx[(tc << 12) + imgoff16(r, k)] = __float2half(src[(size_t)(n >> 1) * 1536 + col]);
    }
    // Wd1: [16 nt][2 c][64x64]
    for (size_t i = t0; i < (size_t)16 * 2 * 4096; i += stride) {
        int k = (int)(i & 63), r = (int)((i >> 6) & 63);
        size_t tc = i >> 12;
        int c = (int)(tc & 1), nt = (int)(tc >> 1);
        g_Wd1i[(tc << 12) + imgoff16(r, k)] =
            __float2half(Wd1[(size_t)(nt * 64 + r) * S + c * 64 + k]);
    }
    // Wd2: [8 nt][16 c][64x64]
    for (size_t i = t0; i < (size_t)8 * 16 * 4096; i += stride) {
        int k = (int)(i & 63), r = (int)((i >> 6) & 63);
        size_t tc = i >> 12;
        int c = (int)(tc & 15), nt = (int)(tc >> 4);
        g_Wd2i[(tc << 12) + imgoff16(r, k)] =
            __float2half(Wd2[(size_t)(nt * 64 + r) * DH + c * 64 + k]);
    }
    // x images: [256 rt][8 c][128x64], row = b*T + t
    for (size_t i = t0; i < (size_t)256 * 8 * 8192; i += stride) {
        int k = (int)(i & 63), r = (int)((i >> 6) & 127);
        size_t tc = i >> 13;
        int c = (int)(tc & 7), rt = (int)(tc >> 3);
        size_t row = (size_t)rt * 128 + r;
        g_xri[(tc << 13) + imgoff16(r, k)] = __float2half(x[row * DIN + c * 64 + k]);
    }
    for (size_t i = t0; i < 4096; i += stride) {
        int j = (int)(i >> 2), g = (int)(i & 3);
        g_bp[i] = bih[g * H + j] + bhh[g * H + j];
    }
}

// ======================= LSTM step: grid (64 nt, 2 mhalf), M64xN64, fused pointwise =======================
__global__ __launch_bounds__(256) void lstm_k(
    const __half* __restrict__ azin, __half* __restrict__ hout)
{
    const int mhalf = blockIdx.y;
    float acc[2][2][4];
    gemm_h<64, 2, 4, 2, 2, 3, 3, 64>(acc, azin + mhalf * 4096, 8192,
                                     g_Wp + (size_t)blockIdx.x * 18 * 4096, 6);

    const int tid = threadIdx.x, t = tid & 31, w = tid >> 5;
    const int wm = w & 1, wn = w >> 1;
    const int m0 = wm * 32, n0 = wn * 16;
    const bool even = (t & 1) == 0;

    #pragma unroll
    for (int mt = 0; mt < 2; mt++)
        #pragma unroll
        for (int nt = 0; nt < 2; nt++)
            #pragma unroll
            for (int rh = 0; rh < 2; rh++) {
                float v0 = acc[mt][nt][rh * 2], v1 = acc[mt][nt][rh * 2 + 1];
                float p0 = __shfl_xor_sync(0xffffffffu, v0, 1);
                float p1 = __shfl_xor_sync(0xffffffffu, v1, 1);
                if (even) {
                    int lc = n0 + nt * 8 + 2 * (t & 3);
                    int pcb = blockIdx.x * 64 + lc;        // gate-interleaved col
                    int j = pcb >> 2;
                    float4 bb = *(const float4*)&g_bp[pcb];
                    int b = mhalf * 64 + m0 + mt * 16 + (t >> 2) + rh * 8;
                    float cold = g_c[b * H + j];
                    float i_ = fsig(v0 + bb.x);
                    float f_ = fsig(v1 + bb.y);
                    float gg = ftanh(p0 + bb.z);
                    float o_ = fsig(p1 + bb.w);
                    float cn = f_ * cold + i_ * gg;
                    g_c[b * H + j] = cn;
                    hout[(j >> 6) * 8192 + imgoff16(b, j & 63)] = __float2half(o_ * ftanh(cn));
                }
            }
}

// ======================= posterior step: grid (16 nt, 2 mhalf), M64xN16 =======================
__global__ __launch_bounds__(256) void post_k(
    const float* __restrict__ noise,
    const float* __restrict__ bm, const float* __restrict__ bv,
    const __half* __restrict__ hin, __half* __restrict__ zout, int ts)
{
    const int mhalf = blockIdx.y;
    float acc[1][1][4];
    gemm_h<16, 4, 2, 1, 1, 4, 3, 64>(acc, hin + mhalf * 4096, 8192,
                                     g_Wmvh + (size_t)blockIdx.x * 16 * 1024, 4);

    __shared__ double klw[8];
    const int tid = threadIdx.x, t = tid & 31, w = tid >> 5;
    const int wm = w & 3, wn = w >> 2;
    const int m0 = wm * 16, n0 = wn * 8;
    const int s = blockIdx.x * 8 + (n0 >> 1) + (t & 3);   // n0/2 + tig; cols 2s,2s+1
    const float bms = bm[s], bvs = bv[s];
    float kl = 0.f;
    #pragma unroll
    for (int rh = 0; rh < 2; rh++) {
        int b = mhalf * 64 + m0 + (t >> 2) + rh * 8;
        const float* pp = g_P + ((size_t)b * T + ts) * 256 + 2 * s;
        float mean = acc[0][0][rh * 2]     + pp[0] + bms;
        float lv   = acc[0][0][rh * 2 + 1] + pp[1] + bvs;
        float sd = __expf(0.5f * fminf(fmaxf(lv, -80.f), 80.f));
        float nz = noise[((size_t)b * T + ts) * S + s];
        zout[(s >> 6) * 8192 + imgoff16(b, s & 63)] = __float2half(nz * sd + mean);
        kl += sd * sd + mean * mean - 0.5f * lv - 0.5f;
    }
    #pragma unroll
    for (int o = 16; o; o >>= 1) kl += __shfl_down_sync(0xffffffffu, kl, o);
    if (t == 0) klw[w] = (double)kl;
    __syncthreads();
    if (tid == 0) {
        double ssum = 0.0;
        #pragma unroll
        for (int i = 0; i < 8; i++) ssum += klw[i];
        g_klpart[(size_t)ts * 32 + mhalf * 16 + blockIdx.x] = ssum;
    }
}

// ======================= postx: P = X @ Wmv[:, :512]^T (all t) =======================
__global__ __launch_bounds__(256) void postx_k() {
    float acc[2][4][4];
    gemm_h<64, 4, 2, 2, 4, 2, 3, 128>(acc, g_xri + (size_t)blockIdx.y * 8 * 8192, 8192,
                                      g_Wmvx + (size_t)blockIdx.x * 8 * 4096, 4);
    const int tid = threadIdx.x, t = tid & 31, w = tid >> 5;
    const int wm = w & 3, wn = w >> 2;
    const int nb = blockIdx.x * 64, rb = blockIdx.y * 128;
    #pragma unroll
    for (int mt = 0; mt < 2; mt++)
        #pragma unroll
        for (int nt = 0; nt < 4; nt++)
            #pragma unroll
            for (int rh = 0; rh < 2; rh++) {
                int row = rb + wm * 32 + mt * 16 + (t >> 2) + rh * 8;
                int col = nb + wn * 32 + nt * 8 + 2 * (t & 3);
                *(float2*)&g_P[(size_t)row * 256 + col] =
                    make_float2(acc[mt][nt][rh * 2], acc[mt][nt][rh * 2 + 1]);
            }
}

// ======================= decoder =======================
__global__ __launch_bounds__(256) void dec1_k(const float* __restrict__ bd1) {
    float acc[2][4][4];
    gemm_h<64, 4, 2, 2, 4, 2, 2, 128>(acc, g_az + (size_t)(blockIdx.y + 1) * AZ_SLOT, 8192,
                                      g_Wd1i + (size_t)blockIdx.x * 2 * 4096, 1);
    const int tid = threadIdx.x, t = tid & 31, w = tid >> 5;
    const int wm = w & 3, wn = w >> 2;
    const int nb = blockIdx.x * 64, rb = blockIdx.y * 128;
    #pragma unroll
    for (int mt = 0; mt < 2; mt++)
        #pragma unroll
        for (int nt = 0; nt < 4; nt++)
            #pragma unroll
            for (int rh = 0; rh < 2; rh++) {
                int row = rb + wm * 32 + mt * 16 + (t >> 2) + rh * 8;   // t*128+b
                int col = nb + wn * 32 + nt * 8 + 2 * (t & 3);
                float v0 = fmaxf(acc[mt][nt][rh * 2]     + bd1[col],     0.f);
                float v1 = fmaxf(acc[mt][nt][rh * 2 + 1] + bd1[col + 1], 0.f);
                int rt = row >> 7, rr = row & 127;
                size_t off = ((size_t)(rt * 16 + (col >> 6)) << 13) + imgoff16(rr, col & 63);
                *(__half2*)&g_hid[off] = __floats2half2_rn(v0, v1);
            }
}

__global__ __launch_bounds__(256) void dec2_k(const float* __restrict__ bd2,
                                              float* __restrict__ out) {
    float acc[2][4][4];
    gemm_h<64, 4, 2, 2, 4, 2, 3, 128>(acc, g_hid + (size_t)blockIdx.y * 16 * 8192, 8192,
                                      g_Wd2i + (size_t)blockIdx.x * 16 * 4096, 8);
    const int tid = threadIdx.x, t = tid & 31, w = tid >> 5;
    const int wm = w & 3, wn = w >> 2;
    const int nb = blockIdx.x * 64, rb = blockIdx.y * 128;
    #pragma unroll
    for (int mt = 0; mt < 2; mt++)
        #pragma unroll
        for (int nt = 0; nt < 4; nt++)
            #pragma unroll
            for (int rh = 0; rh < 2; rh++) {
                int row = rb + wm * 32 + mt * 16 + (t >> 2) + rh * 8;   // t*128+b
                int col = nb + wn * 32 + nt * 8 + 2 * (t & 3);
                int tt = row >> 7, bb = row & 127;
                float v0 = acc[mt][nt][rh * 2]     + bd2[col];
                float v1 = acc[mt][nt][rh * 2 + 1] + bd2[col + 1];
                *(float2*)&out[((size_t)bb * T + tt) * DIN + col] = make_float2(v0, v1);
            }
}

// ======================= final KL reduce =======================
__global__ void kl_kernel(float* __restrict__ out) {
    __shared__ double red[256];
    int tid = threadIdx.x;
    double ssum = 0.0;
    for (int i = tid; i < T * 32; i += 256) ssum += g_klpart[i];
    red[tid] = ssum;
    __syncthreads();
    for (int off = 128; off; off >>= 1) {
        if (tid < off) red[tid] += red[tid + off];
        __syncthreads();
    }
    if (tid == 0) out[(size_t)B * T * DIN] = (float)red[0];
}

// ======================= host =======================
extern "C" void kernel_launch(void* const* d_in, const int* in_sizes, int n_in,
                              void* d_out, int out_size)
{
    const float* x     = (const float*)d_in[0];
    const float* noise = (const float*)d_in[1];
    const float* Wih   = (const float*)d_in[2];
    const float* Whh   = (const float*)d_in[3];
    const float* bih   = (const float*)d_in[4];
    const float* bhh   = (const float*)d_in[5];
    const float* Wm    = (const float*)d_in[6];
    const float* bm    = (const float*)d_in[7];
    const float* Wv    = (const float*)d_in[8];
    const float* bv    = (const float*)d_in[9];
    const float* Wd1   = (const float*)d_in[10];
    const float* bd1   = (const float*)d_in[11];
    const float* Wd2   = (const float*)d_in[12];
    const float* bd2   = (const float*)d_in[13];
    float* out = (float*)d_out;

    const int SM_LSTM = 128 + 3 * (3 * 8192 + 3 * 8192);    // 147584
    const int SM_POST = 128 + 3 * (4 * 8192 + 4 * 2048);    // 123008
    const int SM_BIG  = 128 + 3 * (2 * 16384 + 2 * 8192);   // 147584
    const int SM_DEC1 = 128 + 2 * (2 * 16384 + 2 * 8192);   //  98432
    cudaFuncSetAttribute(lstm_k,  cudaFuncAttributeMaxDynamicSharedMemorySize, SM_LSTM);
    cudaFuncSetAttribute(post_k,  cudaFuncAttributeMaxDynamicSharedMemorySize, SM_POST);
    cudaFuncSetAttribute(postx_k, cudaFuncAttributeMaxDynamicSharedMemorySize, SM_BIG);
    cudaFuncSetAttribute(dec1_k,  cudaFuncAttributeMaxDynamicSharedMemorySize, SM_DEC1);
    cudaFuncSetAttribute(dec2_k,  cudaFuncAttributeMaxDynamicSharedMemorySize, SM_BIG);

    __half* p_az;
    cudaGetSymbolAddress((void**)&p_az, g_az);

    init_kernel<<<256, 256>>>();
    prepack_kernel<<<1024, 256>>>(x, Wih, Whh, bih, bhh, Wm, Wv, Wd1, Wd2);
    postx_k<<<dim3(4, 256), 256, SM_BIG>>>();

    for (int t = 0; t < T; t++) {
        __half* slot_in  = p_az + (size_t)t * AZ_SLOT;
        __half* slot_out = p_az + (size_t)(t + 1) * AZ_SLOT;
        // lstm reads full slot t (z+h images), writes h images (2..17) of slot t+1
        lstm_k<<<dim3(64, 2), 256, SM_LSTM>>>(slot_in, slot_out + 2 * 8192);
        // post reads h images of slot t+1, writes z images (0..1) of slot t+1
        post_k<<<dim3(16, 2), 256, SM_POST>>>(noise, bm, bv, slot_out + 2 * 8192, slot_out, t);
    }
    dec1_k<<<dim3(16, 256), 256, SM_DEC1>>>(bd1);
    dec2_k<<<dim3(8, 256), 256, SM_BIG>>>(bd2, out);
    kl_kernel<<<1, 256>>>(out);
}

// round 14
// speedup vs baseline: 1.2846x; 1.1527x over previous
#include <cuda_runtime.h>
#include <cuda_fp16.h>
#include <cstdint>

#define B   128
#define T   256
#define DIN 512
#define H   1024
#define S   128
#define DH  1024

#define AZ_IMGS 18                       // images per step slot: 2 z + 16 h
#define AZ_SLOT (AZ_IMGS * 8192)         // halves per slot

// ---- scratch (fp16 image layout: tiles of 128 rows x 64 halves, XOR-swizzled) ----
__device__ __half  g_az[(size_t)(T + 1) * AZ_SLOT];  // activation slots: [z0 z1 h0..h15]
__device__ __half  g_hid[(size_t)B * T * DH];        // [256 rt][16 c][128x64]
__device__ float   g_P[(size_t)B * T * 256];         // x-part of posterior, fp32 linear
__device__ __half  g_xri[(size_t)B * T * DIN];       // [256 rt][8 c][128x64]
__device__ __half  g_Wp[(size_t)64 * 18 * 4096];     // lstm W [64 nt][18 c][64x64]
__device__ float   g_bp[4096];                       // bih+bhh gate-interleaved
__device__ __half  g_Wmvh[16 * 16 * 1024];           // post W h-part [16 nt][16 c][16x64]
__device__ __half  g_Wmvx[4 * 8 * 4096];             // postx W [4 nt][8 c][64x64]
__device__ __half  g_Wd1i[16 * 2 * 4096];            // [16 nt][2 c][64x64]
__device__ __half  g_Wd2i[8 * 16 * 4096];            // [8 nt][16 c][64x64]
__device__ double  g_klpart[T * 32];
__device__ int     g_bar[2 * T + 4];                 // grid barrier counters

// ======================= helpers =======================
__device__ __forceinline__ uint32_t smem_u32(const void* p) {
    uint32_t a;
    asm("{ .reg .u64 t; cvta.to.shared.u64 t, %1; cvt.u32.u64 %0, t; }" : "=r"(a) : "l"(p));
    return a;
}
__device__ __forceinline__ int imgoff16(int row, int k) {
    return row * 64 + ((((k >> 3) ^ row) & 7) << 3) + (k & 7);
}

#define MBAR_INIT(a, c) \
    asm volatile("mbarrier.init.shared.b64 [%0], %1;" :: "r"(a), "r"(c) : "memory")

#define MBAR_WAIT(a, ph) do {                                                   \
    uint32_t _m = (a), _p = (uint32_t)(ph), _d;                                 \
    asm volatile("{\n\t.reg .pred p;\n\t"                                       \
        "mbarrier.try_wait.parity.acquire.cta.shared::cta.b64 p, [%1], %2;\n\t" \
        "selp.b32 %0, 1, 0, p;\n\t}"                                            \
        : "=r"(_d) : "r"(_m), "r"(_p) : "memory");                              \
    if (!_d) {                                                                  \
        asm volatile("{\n\t.reg .pred P1;\n\t"                                  \
        "WL%=:\n\t"                                                             \
        "mbarrier.try_wait.parity.acquire.cta.shared::cta.b64 P1, [%0], %1, 0x989680;\n\t" \
        "@P1 bra.uni WD%=;\n\t"                                                 \
        "bra.uni WL%=;\n\t"                                                     \
        "WD%=:\n\t}"                                                            \
        :: "r"(_m), "r"(_p) : "memory");                                        \
    } } while (0)

#define EXPECT_TX(mb, n) \
    asm volatile("mbarrier.arrive.expect_tx.shared.b64 _, [%0], %1;" \
                 :: "r"(mb), "r"((uint32_t)(n)) : "memory")
#define BULK_G2S(dst, src, n, mb) \
    asm volatile("cp.async.bulk.shared::cluster.global.mbarrier::complete_tx::bytes " \
                 "[%0], [%1], %2, [%3];" \
                 :: "r"(dst), "l"(src), "r"((uint32_t)(n)), "r"(mb) : "memory")

__device__ __forceinline__ void ldsm4(uint32_t (&r)[4], uint32_t a) {
    asm volatile("ldmatrix.sync.aligned.m8n8.x4.shared.b16 {%0,%1,%2,%3}, [%4];"
                 : "=r"(r[0]), "=r"(r[1]), "=r"(r[2]), "=r"(r[3]) : "r"(a));
}
__device__ __forceinline__ void ldsm2(uint32_t (&r)[2], uint32_t a) {
    asm volatile("ldmatrix.sync.aligned.m8n8.x2.shared.b16 {%0,%1}, [%2];"
                 : "=r"(r[0]), "=r"(r[1]) : "r"(a));
}
__device__ __forceinline__ void mma16(float (&d)[4], const uint32_t (&a)[4], const uint32_t* b) {
    asm volatile("mma.sync.aligned.m16n8k16.row.col.f32.f16.f16.f32 "
        "{%0,%1,%2,%3}, {%4,%5,%6,%7}, {%8,%9}, {%0,%1,%2,%3};"
        : "+f"(d[0]), "+f"(d[1]), "+f"(d[2]), "+f"(d[3])
        : "r"(a[0]), "r"(a[1]), "r"(a[2]), "r"(a[3]), "r"(b[0]), "r"(b[1]));
}
__device__ __forceinline__ float fsig(float x) {
    float xc = fminf(fmaxf(x, -30.f), 30.f);
    return __fdividef(1.f, 1.f + __expf(-xc));
}
__device__ __forceinline__ float ftanh(float x) {
    float xc = fminf(fmaxf(x, -15.f), 15.f);
    float e = __expf(-2.f * xc);
    return __fdividef(1.f - e, 1.f + e);
}

// ======================= generic bulk-DMA GEMM (used by postx/dec1/dec2) ============
template<int NT, int NWM, int NWN, int MT, int NTT, int KI, int NS, int AROWS>
__device__ __forceinline__ void gemm_h(
    float (&acc)[MT][NTT][4],
    const __half* asrc, size_t a_stride,
    const __half* wsrc, int nchunks)
{
    extern __shared__ char smem[];
    constexpr uint32_t AIMG = (uint32_t)AROWS * 128u;
    constexpr uint32_t AB  = (uint32_t)KI * AIMG;
    constexpr uint32_t WB  = (uint32_t)KI * NT * 128u;
    constexpr uint32_t STG = AB + WB;
    const int tid = threadIdx.x;
    const int t = tid & 31, w = tid >> 5;
    const int wm = w % NWM, wn = w / NWM;
    const int m0 = wm * (AROWS / NWM), n0 = wn * (NT / NWN);
    const uint32_t ctrl = smem_u32(smem);
    const uint32_t base = ctrl + 128;

    #pragma unroll
    for (int mt = 0; mt < MT; mt++)
        #pragma unroll
        for (int nt = 0; nt < NTT; nt++)
            #pragma unroll
            for (int q = 0; q < 4; q++) acc[mt][nt][q] = 0.f;

    int arowb[MT], arx[MT];
    #pragma unroll
    for (int mt = 0; mt < MT; mt++) {
        int r = m0 + mt * 16 + (t & 7) + ((t >> 3) & 1) * 8;
        arowb[mt] = r * 128; arx[mt] = r & 7;
    }
    const int au0 = (t >> 4) & 1;
    constexpr int NP = (NTT + 1) / 2;
    int wrowb[NP], wrx[NP], wu0;
    if constexpr (NTT == 1) {
        int r = n0 + (t & 7);
        wrowb[0] = r * 128; wrx[0] = r & 7; wu0 = (t >> 3) & 1;
    } else {
        #pragma unroll
        for (int p = 0; p < NP; p++) {
            int r = n0 + p * 16 + (t & 7) + ((t >> 4) & 1) * 8;
            wrowb[p] = r * 128; wrx[p] = r & 7;
        }
        wu0 = (t >> 3) & 1;
    }

    if (tid == 0) {
        #pragma unroll
        for (int s = 0; s < NS; s++) MBAR_INIT(ctrl + s * 8, 1);
    }
    __syncthreads();

    auto issue = [&](int c) {
        uint32_t mb = ctrl + (uint32_t)(c % NS) * 8;
        uint32_t ab = base + (uint32_t)(c % NS) * STG;
        EXPECT_TX(mb, AB + WB);
        #pragma unroll
        for (int i = 0; i < KI; i++)
            BULK_G2S(ab + (uint32_t)i * AIMG,
                     asrc + (size_t)(c * KI + i) * a_stride, AIMG, mb);
        BULK_G2S(ab + AB, wsrc + (size_t)c * (KI * NT * 64), WB, mb);
    };
    if (tid == 0)
        for (int i = 0; i < NS - 1 && i < nchunks; i++) issue(i);

    for (int c = 0; c < nchunks; c++) {
        __syncthreads();
        if (tid == 0 && c + NS - 1 < nchunks) issue(c + NS - 1);
        int st = c % NS, ph = (c / NS) & 1;
        MBAR_WAIT(ctrl + (uint32_t)st * 8, ph);
        uint32_t ab = base + (uint32_t)st * STG, wb = ab + AB;
        #pragma unroll
        for (int jj = 0; jj < 4 * KI; jj++) {
            const int img = jj >> 2, j = jj & 3;
            const uint32_t abj = ab + img * AIMG;
            const uint32_t wbj = wb + img * (NT * 128);
            uint32_t afr[MT][4];
            #pragma unroll
            for (int mt = 0; mt < MT; mt++)
                ldsm4(afr[mt], abj + arowb[mt] + (((2 * j + au0) ^ arx[mt]) << 4));
            uint32_t bfr[NTT][2];
            if constexpr (NTT == 1) {
                uint32_t r2[2];
                ldsm2(r2, wbj + wrowb[0] + (((2 * j + wu0) ^ wrx[0]) << 4));
                bfr[0][0] = r2[0]; bfr[0][1] = r2[1];
            } else {
                #pragma unroll
                for (int p = 0; p < NP; p++) {
                    uint32_t r4[4];
                    ldsm4(r4, wbj + wrowb[p] + (((2 * j + wu0) ^ wrx[p]) << 4));
                    bfr[2 * p][0] = r4[0]; bfr[2 * p][1] = r4[1];
                    bfr[2 * p + 1][0] = r4[2]; bfr[2 * p + 1][1] = r4[3];
                }
            }
            #pragma unroll
            for (int mt = 0; mt < MT; mt++)
                #pragma unroll
                for (int nt = 0; nt < NTT; nt++)
                    mma16(acc[mt][nt], afr[mt], bfr[nt]);
        }
    }
}

// ======================= init / prepack =======================
__global__ void init_kernel() {
    int stride = gridDim.x * blockDim.x;
    int t0 = blockIdx.x * blockDim.x + threadIdx.x;
    uint32_t* a0 = (uint32_t*)&g_az[0];
    for (int i = t0; i < AZ_SLOT / 2; i += stride) a0[i] = 0u;
    for (int i = t0; i < 2 * T + 4; i += stride) g_bar[i] = 0;
}

__global__ void prepack_kernel(
    const float* __restrict__ x,
    const float* __restrict__ Wih, const float* __restrict__ Whh,
    const float* __restrict__ bih, const float* __restrict__ bhh,
    const float* __restrict__ Wm, const float* __restrict__ Wv,
    const float* __restrict__ Wd1, const float* __restrict__ Wd2)
{
    size_t stride = (size_t)gridDim.x * blockDim.x;
    size_t t0 = (size_t)blockIdx.x * blockDim.x + threadIdx.x;
    for (size_t i = t0; i < (size_t)64 * 18 * 4096; i += stride) {
        int k = (int)(i & 63), r = (int)((i >> 6) & 63);
        size_t tc = i >> 12;
        int c = (int)(tc % 18), nt = (int)(tc / 18);
        int gc = nt * 64 + r, j = gc >> 2, g = gc & 3, kc = c * 64 + k;
        float v = (kc < S) ? Wih[(size_t)(g * H + j) * S + kc]
                           : Whh[(size_t)(g * H + j) * H + (kc - S)];
        g_Wp[(tc << 12) + imgoff16(r, k)] = __float2half(v);
    }
    for (size_t i = t0; i < (size_t)16 * 16 * 1024; i += stride) {
        int k = (int)(i & 63), r = (int)((i >> 6) & 15);
        size_t tc = i >> 10;
        int c = (int)(tc & 15), nt = (int)(tc >> 4);
        int n = nt * 16 + r, col = 512 + c * 64 + k;
        const float* src = (n & 1) ? Wv : Wm;
        g_Wmvh[(tc << 10) + imgoff16(r, k)] = __float2half(src[(size_t)(n >> 1) * 1536 + col]);
    }
    for (size_t i = t0; i < (size_t)4 * 8 * 4096; i += stride) {
        int k = (int)(i & 63), r = (int)((i >> 6) & 63);
        size_t tc = i >> 12;
        int c = (int)(tc & 7), nt = (int)(tc >> 3);
        int n = nt * 64 + r, col = c * 64 + k;
        const float* src = (n & 1) ? Wv : Wm;
        g_Wmvx[(tc << 12) + imgoff16(r, k)] = __float2half(src[(size_t)(n >> 1) * 1536 + col]);
    }
    for (size_t i = t0; i < (size_t)16 * 2 * 4096; i += stride) {
        int k = (int)(i & 63), r = (int)((i >> 6) & 63);
        size_t tc = i >> 12;
        int c = (int)(tc & 1), nt = (int)(tc >> 1);
        g_Wd1i[(tc << 12) + imgoff16(r, k)] =
            __float2half(Wd1[(size_t)(nt * 64 + r) * S + c * 64 + k]);
    }
    for (size_t i = t0; i < (size_t)8 * 16 * 4096; i += stride) {
        int k = (int)(i & 63), r = (int)((i >> 6) & 63);
        size_t tc = i >> 12;
        int c = (int)(tc & 15), nt = (int)(tc >> 4);
        g_Wd2i[(tc << 12) + imgoff16(r, k)] =
            __float2half(Wd2[(size_t)(nt * 64 + r) * DH + c * 64 + k]);
    }
    for (size_t i = t0; i < (size_t)256 * 8 * 8192; i += stride) {
        int k = (int)(i & 63), r = (int)((i >> 6) & 127);
        size_t tc = i >> 13;
        int c = (int)(tc & 7), rt = (int)(tc >> 3);
        size_t row = (size_t)rt * 128 + r;
        g_xri[(tc << 13) + imgoff16(r, k)] = __float2half(x[row * DIN + c * 64 + k]);
    }
    for (size_t i = t0; i < 4096; i += stride) {
        int j = (int)(i >> 2), g = (int)(i & 3);
        g_bp[i] = bih[g * H + j] + bhh[g * H + j];
    }
}

// ======================= persistent lstm+post over all 256 steps =======================
// grid (64, 2): CTA(nt, mh) = M64 rows [mh*64,...) x N64 gate-cols [nt*64,...).
// W slices SMEM-resident; A streamed per step from L2; 2 grid barriers/step.
__global__ __launch_bounds__(256) void persist_k(
    const float* __restrict__ noise,
    const float* __restrict__ bm, const float* __restrict__ bv)
{
    extern __shared__ char smem[];
    const int tid = threadIdx.x, t = tid & 31, w = tid >> 5;
    const int ntb = blockIdx.x, mh = blockIdx.y;
    const uint32_t ctrl = smem_u32(smem);
    double* klw = (double*)(smem + 24);
    const uint32_t wlstm = ctrl + 128u;               // 147456 B resident lstm W
    const uint32_t wpost = wlstm + 147456u;           // 32768 B resident post W
    const uint32_t ring  = wpost + 32768u;            // 49152 B A ring

    if (tid == 0) { MBAR_INIT(ctrl, 1); MBAR_INIT(ctrl + 8, 1); MBAR_INIT(ctrl + 16, 1); }
    __syncthreads();
    if (tid == 0) {
        uint32_t tx = 147456u + (ntb < 16 ? 32768u : 0u);
        EXPECT_TX(ctrl + 16, tx);
        BULK_G2S(wlstm, (const __half*)g_Wp + (size_t)ntb * 18 * 4096, 147456u, ctrl + 16);
        if (ntb < 16)
            BULK_G2S(wpost, (const __half*)g_Wmvh + (size_t)ntb * 16 * 1024, 32768u, ctrl + 16);
    }
    MBAR_WAIT(ctrl + 16, 0);
    __syncthreads();

    // ---- lstm ldsm offsets (M64xN64: NWM2 NWN4, MT2 NTT2) ----
    const int wmL = w & 1, wnL = w >> 1;
    int arowbL[2], arxL[2];
    #pragma unroll
    for (int mt = 0; mt < 2; mt++) {
        int r = wmL * 32 + mt * 16 + (t & 7) + ((t >> 3) & 1) * 8;
        arowbL[mt] = r * 128; arxL[mt] = r & 7;
    }
    const int au0 = (t >> 4) & 1;
    int rWL = wnL * 16 + (t & 7) + ((t >> 4) & 1) * 8;
    const int wrowbL = rWL * 128, wrxL = rWL & 7, wu0L = (t >> 3) & 1;

    // ---- post ldsm offsets (M64xN16: NWM4 NWN2, MT1 NTT1) ----
    const int wmP = w & 3, wnP = w >> 2;
    int rAP = wmP * 16 + (t & 7) + ((t >> 3) & 1) * 8;
    const int arowbP = rAP * 128, arxP = rAP & 7;
    int rWP = wnP * 8 + (t & 7);
    const int wrowbP = rWP * 128, wrxP = rWP & 7, wu0P = (t >> 3) & 1;

    // ---- hoisted epilogue constants ----
    const bool even = (t & 1) == 0;
    float4 bbv[2];
    if (even) {
        #pragma unroll
        for (int nn = 0; nn < 2; nn++)
            bbv[nn] = *(const float4*)&g_bp[ntb * 64 + wnL * 16 + nn * 8 + 2 * (t & 3)];
    }
    float cr[8];
    #pragma unroll
    for (int i = 0; i < 8; i++) cr[i] = 0.f;

    const int sP = ntb * 8 + wnP * 4 + (t & 3);
    const float bms = (ntb < 16) ? bm[sP] : 0.f;
    const float bvs = (ntb < 16) ? bv[sP] : 0.f;

    int ph0 = 0, ph1 = 0;

    for (int ts = 0; ts < T; ts++) {
        const __half* aslot = (const __half*)g_az + (size_t)ts * AZ_SLOT + (size_t)mh * 4096;
        __half* hout = (__half*)g_az + (size_t)(ts + 1) * AZ_SLOT + 2 * 8192;
        __half* zout = (__half*)g_az + (size_t)(ts + 1) * AZ_SLOT;

        // ================= LSTM phase: 6 chunks of KI=3 (A only; W resident) =========
        float acc[2][2][4];
        #pragma unroll
        for (int mt = 0; mt < 2; mt++)
            #pragma unroll
            for (int nn = 0; nn < 2; nn++)
                #pragma unroll
                for (int q = 0; q < 4; q++) acc[mt][nn][q] = 0.f;

        if (tid == 0) {
            EXPECT_TX(ctrl, 24576u);
            #pragma unroll
            for (int i = 0; i < 3; i++)
                BULK_G2S(ring + (uint32_t)i * 8192u, aslot + (size_t)i * 8192, 8192u, ctrl);
        }
        for (int c = 0; c < 6; c++) {
            __syncthreads();
            if (tid == 0 && c + 1 < 6) {
                int st = (c + 1) & 1;
                uint32_t mb = ctrl + (uint32_t)st * 8u;
                uint32_t ab = ring + (uint32_t)st * 24576u;
                EXPECT_TX(mb, 24576u);
                #pragma unroll
                for (int i = 0; i < 3; i++)
                    BULK_G2S(ab + (uint32_t)i * 8192u,
                             aslot + (size_t)((c + 1) * 3 + i) * 8192, 8192u, mb);
            }
            int st = c & 1;
            int ph = st ? ph1 : ph0;
            MBAR_WAIT(ctrl + (uint32_t)st * 8u, ph);
            if (st) ph1 ^= 1; else ph0 ^= 1;
            uint32_t ab = ring + (uint32_t)st * 24576u;
            #pragma unroll
            for (int jj = 0; jj < 12; jj++) {
                const int img = jj >> 2, j = jj & 3;
                const uint32_t abj = ab + img * 8192u;
                const uint32_t wbj = wlstm + (uint32_t)(c * 3 + img) * 8192u;
                uint32_t afr[2][4];
                #pragma unroll
                for (int mt = 0; mt < 2; mt++)
                    ldsm4(afr[mt], abj + arowbL[mt] + (((2 * j + au0) ^ arxL[mt]) << 4));
                uint32_t r4[4];
                ldsm4(r4, wbj + wrowbL + (((2 * j + wu0L) ^ wrxL) << 4));
                uint32_t bfr[2][2] = {{r4[0], r4[1]}, {r4[2], r4[3]}};
                #pragma unroll
                for (int mt = 0; mt < 2; mt++)
                    #pragma unroll
                    for (int nn = 0; nn < 2; nn++)
                        mma16(acc[mt][nn], afr[mt], bfr[nn]);
            }
        }
        // fused LSTM pointwise epilogue (c in registers)
        #pragma unroll
        for (int mt = 0; mt < 2; mt++)
            #pragma unroll
            for (int nn = 0; nn < 2; nn++)
                #pragma unroll
                for (int rh = 0; rh < 2; rh++) {
                    float v0 = acc[mt][nn][rh * 2], v1 = acc[mt][nn][rh * 2 + 1];
                    float p0 = __shfl_xor_sync(0xffffffffu, v0, 1);
                    float p1 = __shfl_xor_sync(0xffffffffu, v1, 1);
                    if (even) {
                        int pcb = ntb * 64 + wnL * 16 + nn * 8 + 2 * (t & 3);
                        int j = pcb >> 2;
                        float4 bb = bbv[nn];
                        int b = mh * 64 + wmL * 32 + mt * 16 + (t >> 2) + rh * 8;
                        int idx = mt * 4 + nn * 2 + rh;
                        float i_ = fsig(v0 + bb.x);
                        float f_ = fsig(v1 + bb.y);
                        float gg = ftanh(p0 + bb.z);
                        float o_ = fsig(p1 + bb.w);
                        float cn = f_ * cr[idx] + i_ * gg;
                        cr[idx] = cn;
                        hout[(j >> 6) * 8192 + imgoff16(b, j & 63)] = __float2half(o_ * ftanh(cn));
                    }
                }
        // ---- grid barrier 1: h(t+1) ready ----
        __threadfence();
        __syncthreads();
        if (tid == 0) {
            atomicAdd(&g_bar[2 * ts], 1);
            while (((volatile int*)g_bar)[2 * ts] < 128) __nanosleep(64);
        }
        __syncthreads();

        // ================= POST phase (CTAs ntb<16): 8 chunks of KI=2 over h =========
        if (ntb < 16) {
            const __half* hsl = (const __half*)g_az + (size_t)(ts + 1) * AZ_SLOT
                              + 2 * 8192 + (size_t)mh * 4096;
            float pacc[4];
            #pragma unroll
            for (int q = 0; q < 4; q++) pacc[q] = 0.f;
            if (tid == 0) {
                EXPECT_TX(ctrl, 16384u);
                BULK_G2S(ring, hsl, 8192u, ctrl);
                BULK_G2S(ring + 8192u, hsl + 8192, 8192u, ctrl);
            }
            for (int c = 0; c < 8; c++) {
                __syncthreads();
                if (tid == 0 && c + 1 < 8) {
                    int st = (c + 1) & 1;
                    uint32_t mb = ctrl + (uint32_t)st * 8u;
                    uint32_t ab = ring + (uint32_t)st * 16384u;
                    EXPECT_TX(mb, 16384u);
                    BULK_G2S(ab, hsl + (size_t)((c + 1) * 2) * 8192, 8192u, mb);
                    BULK_G2S(ab + 8192u, hsl + (size_t)((c + 1) * 2 + 1) * 8192, 8192u, mb);
                }
                int st = c & 1;
                int ph = st ? ph1 : ph0;
                MBAR_WAIT(ctrl + (uint32_t)st * 8u, ph);
                if (st) ph1 ^= 1; else ph0 ^= 1;
                uint32_t ab = ring + (uint32_t)st * 16384u;
                #pragma unroll
                for (int jj = 0; jj < 8; jj++) {
                    const int img = jj >> 2, j = jj & 3;
                    const uint32_t abj = ab + img * 8192u;
                    const uint32_t wbj = wpost + (uint32_t)(c * 2 + img) * 2048u;
                    uint32_t afr[4];
                    ldsm4(afr, abj + arowbP + (((2 * j + au0) ^ arxP) << 4));
                    uint32_t r2[2];
                    ldsm2(r2, wbj + wrowbP + (((2 * j + wu0P) ^ wrxP) << 4));
                    mma16(pacc, afr, r2);
                }
            }
            // post epilogue
            float kl = 0.f;
            #pragma unroll
            for (int rh = 0; rh < 2; rh++) {
                int b = mh * 64 + wmP * 16 + (t >> 2) + rh * 8;
                const float* pp = g_P + ((size_t)b * T + ts) * 256 + 2 * sP;
                float mean = pacc[rh * 2]     + pp[0] + bms;
                float lv   = pacc[rh * 2 + 1] + pp[1] + bvs;
                float sd = __expf(0.5f * fminf(fmaxf(lv, -80.f), 80.f));
                float nz = noise[((size_t)b * T + ts) * S + sP];
                zout[(sP >> 6) * 8192 + imgoff16(b, sP & 63)] = __float2half(nz * sd + mean);
                kl += sd * sd + mean * mean - 0.5f * lv - 0.5f;
            }
            #pragma unroll
            for (int o = 16; o; o >>= 1) kl += __shfl_down_sync(0xffffffffu, kl, o);
            if (t == 0) klw[w] = (double)kl;
            __syncthreads();
            if (tid == 0) {
                double ssum = 0.0;
                #pragma unroll
                for (int i = 0; i < 8; i++) ssum += klw[i];
                g_klpart[(size_t)ts * 32 + mh * 16 + ntb] = ssum;
            }
        }
        // ---- grid barrier 2: z(t+1) ready ----
        __threadfence();
        __syncthreads();
        if (tid == 0) {
            atomicAdd(&g_bar[2 * ts + 1], 1);
            while (((volatile int*)g_bar)[2 * ts + 1] < 128) __nanosleep(64);
        }
        __syncthreads();
    }
}

// ======================= postx: P = X @ Wmv[:, :512]^T (all t) =======================
__global__ __launch_bounds__(256) void postx_k() {
    float acc[2][4][4];
    gemm_h<64, 4, 2, 2, 4, 2, 3, 128>(acc, g_xri + (size_t)blockIdx.y * 8 * 8192, 8192,
                                      g_Wmvx + (size_t)blockIdx.x * 8 * 4096, 4);
    const int tid = threadIdx.x, t = tid & 31, w = tid >> 5;
    const int wm = w & 3, wn = w >> 2;
    const int nb = blockIdx.x * 64, rb = blockIdx.y * 128;
    #pragma unroll
    for (int mt = 0; mt < 2; mt++)
        #pragma unroll
        for (int nt = 0; nt < 4; nt++)
            #pragma unroll
            for (int rh = 0; rh < 2; rh++) {
                int row = rb + wm * 32 + mt * 16 + (t >> 2) + rh * 8;
                int col = nb + wn * 32 + nt * 8 + 2 * (t & 3);
                *(float2*)&g_P[(size_t)row * 256 + col] =
                    make_float2(acc[mt][nt][rh * 2], acc[mt][nt][rh * 2 + 1]);
            }
}

// ======================= decoder =======================
__global__ __launch_bounds__(256) void dec1_k(const float* __restrict__ bd1) {
    float acc[2][4][4];
    gemm_h<64, 4, 2, 2, 4, 2, 2, 128>(acc, g_az + (size_t)(blockIdx.y + 1) * AZ_SLOT, 8192,
                                      g_Wd1i + (size_t)blockIdx.x * 2 * 4096, 1);
    const int tid = threadIdx.x, t = tid & 31, w = tid >> 5;
    const int wm = w & 3, wn = w >> 2;
    const int nb = blockIdx.x * 64, rb = blockIdx.y * 128;
    #pragma unroll
    for (int mt = 0; mt < 2; mt++)
        #pragma unroll
        for (int nt = 0; nt < 4; nt++)
            #pragma unroll
            for (int rh = 0; rh < 2; rh++) {
                int row = rb + wm * 32 + mt * 16 + (t >> 2) + rh * 8;
                int col = nb + wn * 32 + nt * 8 + 2 * (t & 3);
                float v0 = fmaxf(acc[mt][nt][rh * 2]     + bd1[col],     0.f);
                float v1 = fmaxf(acc[mt][nt][rh * 2 + 1] + bd1[col + 1], 0.f);
                int rt = row >> 7, rr = row & 127;
                size_t off = ((size_t)(rt * 16 + (col >> 6)) << 13) + imgoff16(rr, col & 63);
                *(__half2*)&g_hid[off] = __floats2half2_rn(v0, v1);
            }
}

__global__ __launch_bounds__(256) void dec2_k(const float* __restrict__ bd2,
                                              float* __restrict__ out) {
    float acc[2][4][4];
    gemm_h<64, 4, 2, 2, 4, 2, 3, 128>(acc, g_hid + (size_t)blockIdx.y * 16 * 8192, 8192,
                                      g_Wd2i + (size_t)blockIdx.x * 16 * 4096, 8);
    const int tid = threadIdx.x, t = tid & 31, w = tid >> 5;
    const int wm = w & 3, wn = w >> 2;
    const int nb = blockIdx.x * 64, rb = blockIdx.y * 128;
    #pragma unroll
    for (int mt = 0; mt < 2; mt++)
        #pragma unroll
        for (int nt = 0; nt < 4; nt++)
            #pragma unroll
            for (int rh = 0; rh < 2; rh++) {
                int row = rb + wm * 32 + mt * 16 + (t >> 2) + rh * 8;
                int col = nb + wn * 32 + nt * 8 + 2 * (t & 3);
                int tt = row >> 7, bb = row & 127;
                float v0 = acc[mt][nt][rh * 2]     + bd2[col];
                float v1 = acc[mt][nt][rh * 2 + 1] + bd2[col + 1];
                *(float2*)&out[((size_t)bb * T + tt) * DIN + col] = make_float2(v0, v1);
            }
}

// ======================= final KL reduce =======================
__global__ void kl_kernel(float* __restrict__ out) {
    __shared__ double red[256];
    int tid = threadIdx.x;
    double ssum = 0.0;
    for (int i = tid; i < T * 32; i += 256) ssum += g_klpart[i];
    red[tid] = ssum;
    __syncthreads();
    for (int off = 128; off; off >>= 1) {
        if (tid < off) red[tid] += red[tid + off];
        __syncthreads();
    }
    if (tid == 0) out[(size_t)B * T * DIN] = (float)red[0];
}

// ======================= host =======================
extern "C" void kernel_launch(void* const* d_in, const int* in_sizes, int n_in,
                              void* d_out, int out_size)
{
    const float* x     = (const float*)d_in[0];
    const float* noise = (const float*)d_in[1];
    const float* Wih   = (const float*)d_in[2];
    const float* Whh   = (const float*)d_in[3];
    const float* bih   = (const float*)d_in[4];
    const float* bhh   = (const float*)d_in[5];
    const float* Wm    = (const float*)d_in[6];
    const float* bm    = (const float*)d_in[7];
    const float* Wv    = (const float*)d_in[8];
    const float* bv    = (const float*)d_in[9];
    const float* Wd1   = (const float*)d_in[10];
    const float* bd1   = (const float*)d_in[11];
    const float* Wd2   = (const float*)d_in[12];
    const float* bd2   = (const float*)d_in[13];
    float* out = (float*)d_out;

    const int SM_PERS = 128 + 147456 + 32768 + 49152;       // 229504
    const int SM_BIG  = 128 + 3 * (2 * 16384 + 2 * 8192);   // 147584
    const int SM_DEC1 = 128 + 2 * (2 * 16384 + 2 * 8192);   //  98432
    cudaFuncSetAttribute(persist_k, cudaFuncAttributeMaxDynamicSharedMemorySize, SM_PERS);
    cudaFuncSetAttribute(postx_k,   cudaFuncAttributeMaxDynamicSharedMemorySize, SM_BIG);
    cudaFuncSetAttribute(dec1_k,    cudaFuncAttributeMaxDynamicSharedMemorySize, SM_DEC1);
    cudaFuncSetAttribute(dec2_k,    cudaFuncAttributeMaxDynamicSharedMemorySize, SM_BIG);

    init_kernel<<<256, 256>>>();
    prepack_kernel<<<1024, 256>>>(x, Wih, Whh, bih, bhh, Wm, Wv, Wd1, Wd2);
    postx_k<<<dim3(4, 256), 256, SM_BIG>>>();

    persist_k<<<dim3(64, 2), 256, SM_PERS>>>(noise, bm, bv);

    dec1_k<<<dim3(16, 256), 256, SM_DEC1>>>(bd1);
    dec2_k<<<dim3(8, 256), 256, SM_BIG>>>(bd2, out);
    kl_kernel<<<1, 256>>>(out);
}